// round 10
// baseline (speedup 1.0000x reference)
#include <cuda_runtime.h>
#include <cstdint>

// Problem constants
#define BB   4      // batch
#define CIN  3
#define C1   32     // conv1 out channels (16x16 spatial)
#define C2   64     // conv2 out channels (8x8 spatial)
#define MM   512    // hopfield memory slots
#define DD   64     // token dim (== C2)
#define NTOK 2      // tokens per block
#define THR  512    // threads per block
#define NBLK 128    // 4 samples x 32 token-pairs; fully independent blocks
#define LSTR 68     // Lsm row stride (floats): 16B-aligned, conflict-free

// Shared memory layout (float offsets).
#define LSM_OFF   0                        // 512*68 = 34816
#define WVS_OFF   34816                    // 64*64  = 4096
#define WOS_OFF   38912                    // 64*64  = 4096
#define PS2_OFF   43008                    // 512 float2 = 1024 f
#define PART2_OFF 44032                    // 512 float2 = 1024 f
#define ZQ_OFF    45056                    // [2][64] tokens / tmp = 128 f
#define S1_OFF    45184                    // [2][64] = 128 f
#define OS2_OFF   45312                    // 64 float2 = 128 f
#define RED_OFF   45440                    // 40 f reduce scratch
#define XPAD_OFF  45480                    // 3*34*34 = 3468 f
#define AW_OFF    48948                    // 32*25 = 800 f (stride-25 conflict-free)
#define VW_OFF    49748                    // 32*25 = 800 f
#define W1S_OFF   50548                    // 32*3*16 = 1536 f
#define SMEM_FLOATS 52084                  // 208336 bytes

// ---- cp.async helpers (sm_80+; LDGSTS on sm_103a) -------------------------
__device__ __forceinline__ void cp_async16(uint32_t dst, const void* src) {
    asm volatile("cp.async.ca.shared.global [%0], [%1], 16;"
                 :: "r"(dst), "l"(src));
}
__device__ __forceinline__ void cp_async4(uint32_t dst, const void* src) {
    asm volatile("cp.async.ca.shared.global [%0], [%1], 4;"
                 :: "r"(dst), "l"(src));
}
__device__ __forceinline__ void cp_commit() {
    asm volatile("cp.async.commit_group;");
}
template <int N>
__device__ __forceinline__ void cp_wait() {
    asm volatile("cp.async.wait_group %0;" :: "n"(N));
}

__global__ __launch_bounds__(THR, 1)
void fused_kernel(const float* __restrict__ x,
                  const float* __restrict__ w1,
                  const float* __restrict__ b1,
                  const float* __restrict__ w2,
                  const float* __restrict__ b2,
                  const float* __restrict__ lookup,
                  const float* __restrict__ Wv,
                  const float* __restrict__ Wo,
                  float* __restrict__ out) {
    extern __shared__ float smem[];
    float*  Lsm   = smem + LSM_OFF;
    float*  WvS   = smem + WVS_OFF;
    float*  WoS   = smem + WOS_OFF;
    float2* pS2   = (float2*)(smem + PS2_OFF);
    float2* part2 = (float2*)(smem + PART2_OFF);
    float*  zqS   = smem + ZQ_OFF;        // [j][64]: tokens, later tmp
    float*  s1S   = smem + S1_OFF;        // [j][64]: first projection
    float2* oS2   = (float2*)(smem + OS2_OFF);
    float2* red2  = (float2*)(smem + RED_OFF);
    float*  xpad  = smem + XPAD_OFF;      // [3][34][34] zero-padded input
    float*  aW    = smem + AW_OFF;        // conv1 window, relu(pre)
    float*  vW    = smem + VW_OFF;        // conv1 window, masked JVP
    float*  w1S   = smem + W1S_OFF;       // conv1 weights

    const uint32_t sb = (uint32_t)__cvta_generic_to_shared(smem);

    int tid  = threadIdx.x;
    int lane = tid & 31;
    int wid  = tid >> 5;
    int blk  = blockIdx.x;
    int b    = blk >> 5;                  // sample
    int tg   = blk & 31;                  // token group
    int n0   = tg * NTOK;
    int oy   = n0 >> 3;                   // both tokens share oy (n0 even)
    int ox0  = n0 & 7;

    // ===== zero xpad (STS), then sync so cp.async can overwrite interior ===
    #pragma unroll
    for (int it = 0; it < 7; it++) {
        int i = it*THR + tid;
        if (i < 3*34*34) xpad[i] = 0.f;
    }
    __syncthreads();

    // ===== Group A: xpad interior + w1 -> smem (needed by conv1) ===========
    {
        const float* xb = x + b * CIN * 1024;
        #pragma unroll
        for (int it = 0; it < 6; it++) {
            int i = it*THR + tid;                  // < 3072
            int ic = i >> 10, r = (i >> 5) & 31, c = i & 31;
            cp_async4(sb + (XPAD_OFF + (ic*34 + r + 1)*34 + c + 1)*4, &xb[i]);
        }
        if (tid < 384)                             // 1536 floats = 384 x 16B
            cp_async16(sb + W1S_OFF*4 + tid*16, (const char*)w1 + tid*16);
    }
    cp_commit();

    // ===== Group B: lookup -> Lsm (padded), Wv/Wo -> smem ==================
    {
        const float4* L4 = (const float4*)lookup;
        #pragma unroll
        for (int u = 0; u < 16; u++) {
            int f = u*THR + tid;                   // float4 index 0..8191
            cp_async16(sb + LSM_OFF*4 + ((f >> 4)*17 + (f & 15))*16,
                       &L4[f]);
        }
        cp_async16(sb + WVS_OFF*4 + tid*16,        (const char*)Wv + tid*16);
        cp_async16(sb + WVS_OFF*4 + (THR+tid)*16,  (const char*)Wv + (THR+tid)*16);
        cp_async16(sb + WOS_OFF*4 + tid*16,        (const char*)Wo + tid*16);
        cp_async16(sb + WOS_OFF*4 + (THR+tid)*16,  (const char*)Wo + (THR+tid)*16);
    }
    cp_commit();

    cp_wait<1>();          // group A (xpad + w1) complete; B still in flight
    __syncthreads();

    // ===== Phase 1: conv1 for the 4x6 window this block needs ==============
    for (int e = tid; e < 32*24; e += THR) {
        int ic  = e / 24;
        int pos = e - ic*24;
        int ri  = pos / 6;
        int ci  = pos - ri*6;
        int r = 2*oy - 1 + ri;
        int c = 2*ox0 - 1 + ci;
        float aVal = 0.f, vVal = 0.f;
        if ((unsigned)r < 16u && (unsigned)c < 16u) {
            float s = 0.f;
            #pragma unroll
            for (int cin = 0; cin < CIN; cin++) {
                const float* base = &xpad[(cin*34 + 2*r)*34 + 2*c];
                const float4* wp4 = (const float4*)&w1S[(ic*CIN + cin)*16];
                #pragma unroll
                for (int ky = 0; ky < 4; ky++) {
                    float4 w4 = wp4[ky];
                    const float* row = base + ky*34;
                    s += row[0]*w4.x + row[1]*w4.y + row[2]*w4.z + row[3]*w4.w;
                }
            }
            float pre = s + __ldg(&b1[ic]);
            if (pre > 0.f) { aVal = pre; vVal = s; }
        }
        aW[ic*25 + pos] = aVal;
        vW[ic*25 + pos] = vVal;
    }
    __syncthreads();

    // ===== Phase 2: conv2.  thread = (oc, ic-octet), computes BOTH tokens ==
    {
        int oc  = tid >> 3;          // 0..63
        int ich = tid & 7;           // ic octet 0..7 (low bits -> shfl-local)
        float sA0 = 0.f, sV0 = 0.f, sA1 = 0.f, sV1 = 0.f;
        #pragma unroll
        for (int i = 0; i < 4; i++) {
            int ic = ich*4 + i;
            const float*  ar  = &aW[ic*25];
            const float*  vr  = &vW[ic*25];
            const float4* wp4 = (const float4*)&w2[(oc*C1 + ic)*16];
            #pragma unroll
            for (int ky = 0; ky < 4; ky++) {
                float4 w4 = __ldg(&wp4[ky]);
                const float* a = &ar[ky*6];
                const float* v = &vr[ky*6];
                float a0=a[0],a1=a[1],a2=a[2],a3=a[3],a4=a[4],a5=a[5];
                float v0=v[0],v1=v[1],v2=v[2],v3=v[3],v4=v[4],v5=v[5];
                sA0 += a0*w4.x + a1*w4.y + a2*w4.z + a3*w4.w;
                sV0 += v0*w4.x + v1*w4.y + v2*w4.z + v3*w4.w;
                sA1 += a2*w4.x + a3*w4.y + a4*w4.z + a5*w4.w;
                sV1 += v2*w4.x + v3*w4.y + v4*w4.z + v5*w4.w;
            }
        }
        #pragma unroll
        for (int off = 1; off <= 4; off <<= 1) {
            sA0 += __shfl_xor_sync(0xFFFFFFFFu, sA0, off);
            sV0 += __shfl_xor_sync(0xFFFFFFFFu, sV0, off);
            sA1 += __shfl_xor_sync(0xFFFFFFFFu, sA1, off);
            sV1 += __shfl_xor_sync(0xFFFFFFFFu, sV1, off);
        }
        if (ich == 0) {
            float bb = __ldg(&b2[oc]);
            float p0 = sA0 + bb;
            float p1 = sA1 + bb;
            zqS[oc]      = (p0 > 0.f) ? sV0 : 0.f;
            zqS[DD + oc] = (p1 > 0.f) ? sV1 : 0.f;
        }
    }
    cp_wait<0>();          // lookup / Wv / Wo staged (overlapped with convs)
    __syncthreads();

    // ===== Phase 3: hopfield ==============================================
    // scores: thread owns row m = tid, both tokens
    float a0 = 0.f, a1 = 0.f;
    {
        const float4* lrow = (const float4*)&Lsm[tid*LSTR];
        const float4* t0p  = (const float4*)&zqS[0];
        const float4* t1p  = (const float4*)&zqS[DD];
        #pragma unroll
        for (int q = 0; q < 16; q++) {
            float4 l  = lrow[q];
            float4 t0 = t0p[q];
            float4 t1 = t1p[q];
            a0 += l.x*t0.x + l.y*t0.y + l.z*t0.z + l.w*t0.w;
            a1 += l.x*t1.x + l.y*t1.y + l.z*t1.z + l.w*t1.w;
        }
    }
    a0 *= 0.125f; a1 *= 0.125f;   // 1/sqrt(64)

    // block max
    {
        float mx0 = a0, mx1 = a1;
        #pragma unroll
        for (int o = 16; o > 0; o >>= 1) {
            mx0 = fmaxf(mx0, __shfl_xor_sync(0xFFFFFFFFu, mx0, o));
            mx1 = fmaxf(mx1, __shfl_xor_sync(0xFFFFFFFFu, mx1, o));
        }
        if (lane == 0) red2[wid] = make_float2(mx0, mx1);
    }
    __syncthreads();
    if (tid < 32) {
        float2 v = (lane < 16) ? red2[lane] : make_float2(-1e30f, -1e30f);
        #pragma unroll
        for (int o = 8; o > 0; o >>= 1) {
            v.x = fmaxf(v.x, __shfl_xor_sync(0xFFFFFFFFu, v.x, o));
            v.y = fmaxf(v.y, __shfl_xor_sync(0xFFFFFFFFu, v.y, o));
        }
        if (lane == 0) red2[16] = v;
    }
    __syncthreads();
    float2 MX = red2[16];

    // exp + block sum
    float e0 = __expf(a0 - MX.x);
    float e1 = __expf(a1 - MX.y);
    pS2[tid] = make_float2(e0, e1);
    {
        float s0 = e0, s1 = e1;
        #pragma unroll
        for (int o = 16; o > 0; o >>= 1) {
            s0 += __shfl_xor_sync(0xFFFFFFFFu, s0, o);
            s1 += __shfl_xor_sync(0xFFFFFFFFu, s1, o);
        }
        if (lane == 0) red2[wid] = make_float2(s0, s1);
    }
    __syncthreads();
    if (tid < 32) {
        float2 v = (lane < 16) ? red2[lane] : make_float2(0.f, 0.f);
        #pragma unroll
        for (int o = 8; o > 0; o >>= 1) {
            v.x += __shfl_xor_sync(0xFFFFFFFFu, v.x, o);
            v.y += __shfl_xor_sync(0xFFFFFFFFu, v.y, o);
        }
        if (lane == 0) red2[17] = v;
    }
    __syncthreads();
    float2 SUM = red2[17];

    // retrieval: part[c][d] = sum over 64 m of p[m]*L[m][d]
    {
        int d = tid & 63, c = tid >> 6;   // 8 chunks of 64 m
        float r0 = 0.f, r1 = 0.f;
        int m0 = c * 64;
        #pragma unroll 8
        for (int mm = 0; mm < 64; mm++) {
            float2 p = pS2[m0 + mm];              // broadcast
            float  l = Lsm[(m0 + mm)*LSTR + d];   // conflict-free
            r0 += p.x*l; r1 += p.y*l;
        }
        part2[c*64 + d] = make_float2(r0, r1);
    }
    __syncthreads();
    if (tid < NTOK*DD) {
        int j = tid >> 6, d = tid & 63;
        const float* pf = (const float*)part2;
        float s = 0.f;
        #pragma unroll
        for (int c = 0; c < 8; c++)
            s += pf[(c*64 + d)*2 + j];
        float inv = 1.f / (j ? SUM.y : SUM.x);
        zqS[j*DD + d] = s * inv;                  // tmp[j][d] (zqS reused)
    }
    __syncthreads();

    // projection 1: s1[j][f] = sum_d tmp[j][d] * Wv[d][f]
    if (tid < NTOK*DD) {
        int j = tid >> 6, f = tid & 63;
        float s = 0.f;
        const float* tp = &zqS[j*DD];
        #pragma unroll 16
        for (int d = 0; d < DD; d++)
            s += tp[d] * WvS[d*DD + f];           // bcast + conflict-free
        s1S[j*DD + f] = s;
    }
    __syncthreads();

    // projection 2: out[j][e] = sum_f s1[j][f] * Wo[f][e]
    if (tid < NTOK*DD) {
        int j = tid >> 6, e = tid & 63;
        float o = 0.f;
        const float* sp = &s1S[j*DD];
        #pragma unroll 16
        for (int f = 0; f < DD; f++)
            o += sp[f] * WoS[f*DD + e];
        ((float*)&oS2[e])[j] = o;
    }
    __syncthreads();
    if (tid < DD) {
        float2 ov = oS2[tid];
        *(float2*)&out[(b*C2 + tid)*64 + n0] = ov;
    }
}

// ---------------------------------------------------------------------------
extern "C" void kernel_launch(void* const* d_in, const int* in_sizes, int n_in,
                              void* d_out, int out_size) {
    const float* x       = (const float*)d_in[0];
    const float* conv1_w = (const float*)d_in[1];
    const float* conv1_b = (const float*)d_in[2];
    const float* conv2_w = (const float*)d_in[3];
    const float* conv2_b = (const float*)d_in[4];
    const float* lookup  = (const float*)d_in[5];
    const float* Wv      = (const float*)d_in[6];
    const float* Wo      = (const float*)d_in[7];
    float* out = (float*)d_out;

    const size_t smem_bytes = SMEM_FLOATS * sizeof(float);

    cudaFuncSetAttribute(fused_kernel,
                         cudaFuncAttributeMaxDynamicSharedMemorySize,
                         (int)smem_bytes);
    cudaFuncSetAttribute(fused_kernel,
                         cudaFuncAttributePreferredSharedMemoryCarveout, 100);

    fused_kernel<<<NBLK, THR, smem_bytes>>>(
        x, conv1_w, conv1_b, conv2_w, conv2_b, lookup, Wv, Wo, out);
}